// round 1
// baseline (speedup 1.0000x reference)
#include <cuda_runtime.h>
#include <cstdint>

// Fixed problem maxima (from reference): 1M edges, 100K nodes, 2M pairs.
#define NE_MAX 1000000
#define NN_MAX 100000

// Scratch: allocation-free rule -> __device__ globals.
__device__ float g_P[(size_t)NE_MAX * 64];   // per-edge projection  edge_attr @ W_edge[:, :64]^T
__device__ float g_Q[(size_t)NN_MAX * 64];   // per-node projection  [x|gs]    @ W_edge[:, 64:]^T

__device__ __forceinline__ float eluf(float x) {
    return x > 0.f ? x : (__expf(x) - 1.f);
}

// ---------------------------------------------------------------------------
// K1: Q[n][o] = sum_i xg[n][i] * W_edge[o][64+i],  xg = [x (37) | gs (5)]
// ---------------------------------------------------------------------------
__global__ void node_proj_kernel(const float* __restrict__ x,
                                 const float* __restrict__ gs,
                                 const float* __restrict__ W_edge,
                                 int NN) {
    __shared__ float Wn[64 * 42];
    int tid = threadIdx.x;
    for (int s = tid; s < 64 * 42; s += blockDim.x) {
        int o = s / 42, i = s % 42;
        Wn[s] = W_edge[o * 106 + 64 + i];
    }
    __syncthreads();

    int gid = blockIdx.x * blockDim.x + tid;
    int n = gid >> 6, o = gid & 63;
    if (n >= NN) return;

    const float* xr = x + (size_t)n * 37;
    const float* gr = gs + (size_t)n * 5;
    const float* w  = Wn + o * 42;
    float acc = 0.f;
#pragma unroll
    for (int i = 0; i < 37; i++) acc = fmaf(xr[i], w[i], acc);
#pragma unroll
    for (int j = 0; j < 5; j++) acc = fmaf(gr[j], w[37 + j], acc);
    g_Q[(size_t)n * 64 + o] = acc;
}

// ---------------------------------------------------------------------------
// K2: combined GEMM  [NE,64] x [64,128]:
//   cols   0..63  -> out  = elu(E @ W_e^T + b_e)
//   cols  64..127 -> g_P  = E @ W_edge[:, :64]^T        (no bias/activation)
// Register-tiled 128x128 block tile, 8x8 per thread, grid-stride persistent.
// ---------------------------------------------------------------------------
#define SAS 132   // padded stride for transposed A tile (float4-aligned, bank-spread)

__global__ __launch_bounds__(256, 2) void edge_gemm_kernel(
    const float* __restrict__ E,
    const float* __restrict__ W_edge,
    const float* __restrict__ W_e,
    const float* __restrict__ b_e,
    float* __restrict__ out,
    int NE) {
    extern __shared__ float sm[];
    float* As = sm;               // [64][SAS]  transposed A tile: As[k][row]
    float* Ws = sm + 64 * SAS;    // [64][128]  transposed weights: Ws[k][o]

    int tid = threadIdx.x;

    // Load combined weight matrix once per block (persistent grid amortizes).
    for (int s = tid; s < 64 * 128; s += 256) {
        int k = s >> 7, o = s & 127;
        float w = (o < 64) ? W_e[o * 64 + k] : W_edge[(o - 64) * 106 + k];
        Ws[k * 128 + o] = w;
    }

    int tr = tid >> 4;   // 0..15 -> rows  tr*8 .. tr*8+7
    int tc = tid & 15;   // 0..15 -> cols  tc*8 .. tc*8+7

    int ntiles = (NE + 127) >> 7;
    for (int t = blockIdx.x; t < ntiles; t += gridDim.x) {
        int row0 = t << 7;
        __syncthreads();   // protect As from previous tile's readers (also covers Ws on t0)

        // Stage A tile transposed: As[k][row]
#pragma unroll
        for (int i = 0; i < 8; i++) {
            int s  = tid + i * 256;
            int r  = s >> 4, kq = s & 15;
            int row = row0 + r;
            float4 v = make_float4(0.f, 0.f, 0.f, 0.f);
            if (row < NE) v = *(const float4*)&E[(size_t)row * 64 + kq * 4];
            As[(kq * 4 + 0) * SAS + r] = v.x;
            As[(kq * 4 + 1) * SAS + r] = v.y;
            As[(kq * 4 + 2) * SAS + r] = v.z;
            As[(kq * 4 + 3) * SAS + r] = v.w;
        }
        __syncthreads();

        float acc[64];
#pragma unroll
        for (int i = 0; i < 64; i++) acc[i] = 0.f;

#pragma unroll 4
        for (int k = 0; k < 64; k++) {
            float a[8], w[8];
            *(float4*)(a)     = *(const float4*)&As[k * SAS + tr * 8];
            *(float4*)(a + 4) = *(const float4*)&As[k * SAS + tr * 8 + 4];
            *(float4*)(w)     = *(const float4*)&Ws[k * 128 + tc * 8];
            *(float4*)(w + 4) = *(const float4*)&Ws[k * 128 + tc * 8 + 4];
#pragma unroll
            for (int i = 0; i < 8; i++)
#pragma unroll
                for (int j = 0; j < 8; j++)
                    acc[i * 8 + j] = fmaf(a[i], w[j], acc[i * 8 + j]);
        }

        if (tc < 8) {
            // out half: add bias, elu
            float bb[8];
#pragma unroll
            for (int j = 0; j < 8; j++) bb[j] = __ldg(&b_e[tc * 8 + j]);
#pragma unroll
            for (int i = 0; i < 8; i++) {
                int row = row0 + tr * 8 + i;
                if (row < NE) {
                    float4 v0, v1;
                    v0.x = eluf(acc[i * 8 + 0] + bb[0]);
                    v0.y = eluf(acc[i * 8 + 1] + bb[1]);
                    v0.z = eluf(acc[i * 8 + 2] + bb[2]);
                    v0.w = eluf(acc[i * 8 + 3] + bb[3]);
                    v1.x = eluf(acc[i * 8 + 4] + bb[4]);
                    v1.y = eluf(acc[i * 8 + 5] + bb[5]);
                    v1.z = eluf(acc[i * 8 + 6] + bb[6]);
                    v1.w = eluf(acc[i * 8 + 7] + bb[7]);
                    *(float4*)&out[(size_t)row * 64 + tc * 8]     = v0;
                    *(float4*)&out[(size_t)row * 64 + tc * 8 + 4] = v1;
                }
            }
        } else {
            // P half: raw projection
            int c0 = tc * 8 - 64;
#pragma unroll
            for (int i = 0; i < 8; i++) {
                int row = row0 + tr * 8 + i;
                if (row < NE) {
                    float4 v0 = make_float4(acc[i * 8 + 0], acc[i * 8 + 1],
                                            acc[i * 8 + 2], acc[i * 8 + 3]);
                    float4 v1 = make_float4(acc[i * 8 + 4], acc[i * 8 + 5],
                                            acc[i * 8 + 6], acc[i * 8 + 7]);
                    *(float4*)&g_P[(size_t)row * 64 + c0]     = v0;
                    *(float4*)&g_P[(size_t)row * 64 + c0 + 4] = v1;
                }
            }
        }
    }
}

// ---------------------------------------------------------------------------
// K3: per pair k:  h = elu(P[e1] + Q[a0] + b_edge);  out[e0] += h
// 16 threads per pair, float4 lanes, vector red.global scatter.
// ---------------------------------------------------------------------------
__global__ void pair_scatter_kernel(const float* __restrict__ b_edge,
                                    const int* __restrict__ aidx,   // atom_index base (row0 used)
                                    const int* __restrict__ eidx,   // e_idx base (rows 0 and 1)
                                    float* __restrict__ out,
                                    int NP) {
    __shared__ float bs[64];
    int tid = threadIdx.x;
    if (tid < 64) bs[tid] = b_edge[tid];
    __syncthreads();

    int pl = tid >> 4;           // pair-local 0..15
    int q  = tid & 15;           // quarter 0..15 -> channels q*4..q*4+3
    long long k = (long long)blockIdx.x * 16 + pl;
    if (k >= NP) return;

    int e0 = eidx[k];
    int e1 = eidx[(size_t)NP + k];
    int a0 = aidx[k];

    float4 p  = __ldg((const float4*)&g_P[(size_t)e1 * 64 + q * 4]);
    float4 qv = __ldg((const float4*)&g_Q[(size_t)a0 * 64 + q * 4]);

    float h0 = eluf(p.x + qv.x + bs[q * 4 + 0]);
    float h1 = eluf(p.y + qv.y + bs[q * 4 + 1]);
    float h2 = eluf(p.z + qv.z + bs[q * 4 + 2]);
    float h3 = eluf(p.w + qv.w + bs[q * 4 + 3]);

    float* addr = out + (size_t)e0 * 64 + q * 4;
    asm volatile("red.global.add.v4.f32 [%0], {%1,%2,%3,%4};"
                 :: "l"(addr), "f"(h0), "f"(h1), "f"(h2), "f"(h3)
                 : "memory");
}

// ---------------------------------------------------------------------------
extern "C" void kernel_launch(void* const* d_in, const int* in_sizes, int n_in,
                              void* d_out, int out_size) {
    const float* x      = (const float*)d_in[0];
    const float* gs     = (const float*)d_in[1];
    const float* E      = (const float*)d_in[2];
    const float* W_edge = (const float*)d_in[3];
    const float* b_edge = (const float*)d_in[4];
    const float* W_e    = (const float*)d_in[5];
    const float* b_e    = (const float*)d_in[6];
    const int*   aidx   = (const int*)d_in[7];
    const int*   eidx   = (const int*)d_in[8];
    float* out = (float*)d_out;

    int NN = in_sizes[0] / 37;
    int NE = in_sizes[2] / 64;
    int NP = in_sizes[7] / 2;
    if (NN > NN_MAX) NN = NN_MAX;
    if (NE > NE_MAX) NE = NE_MAX;

    // K1: node projections -> g_Q
    int t1 = (NN * 64 + 255) / 256;
    node_proj_kernel<<<t1, 256>>>(x, gs, W_edge, NN);

    // K2: fused edge GEMM -> out (elu half) + g_P
    const int smem_bytes = (64 * SAS + 64 * 128) * (int)sizeof(float);  // 66560
    cudaFuncSetAttribute(edge_gemm_kernel,
                         cudaFuncAttributeMaxDynamicSharedMemorySize, smem_bytes);
    edge_gemm_kernel<<<296, 256, smem_bytes>>>(E, W_edge, W_e, b_e, out, NE);

    // K3: pair gather + elu + vector-red scatter
    int t3 = (NP + 15) / 16;
    pair_scatter_kernel<<<t3, 256>>>(b_edge, aidx, eidx, out, NP);
}